// round 6
// baseline (speedup 1.0000x reference)
#include <cuda_runtime.h>
#include <cstdint>

// Problem constants
#define ODIM 4096
#define IDIM 4096
#define MTOT 8192   // B*S = 4*2048
#define SEQ  2048

#define KC 128                 // k per chunk: 128 int8 = 128B row = SW128 atom = scale group
#define NCHUNK (IDIM / KC)     // 32
#define F_STAGES 4

// Shared memory layout
#define SMEM_FULL  8           // 4 x 8B full barriers (complete_tx)
#define SMEM_EMPTY 64          // 4 x 8B empty barriers (count=256)
#define SMEM_DATA  1024
#define TILE_BYTES 16384       // 128 rows x 128B
#define WS_BYTES   1024        // 256 floats of wscale for this (n-tile, group)
#define STAGE_BYTES (3 * TILE_BYTES + WS_BYTES)          // 50176: A + B0 + B1 + ws
#define SMEM_TOTAL  (1024 + F_STAGES * STAGE_BYTES)      // 201728

// Tiled, pre-swizzled int8 operands: tile (row128, kchunk) = 16KB contiguous.
__device__ int8_t g_Xt8[(size_t)MTOT * IDIM];   // 32 MB  (64 m-tiles x 32 chunks)
__device__ int8_t g_Wt8[(size_t)ODIM * IDIM];   // 16 MB  (32 n-tiles x 32 chunks)
__device__ float  g_WsT[32 * ODIM];             // wscale transposed: [group][n]

// ---------------------------------------------------------------------------
// helpers
// ---------------------------------------------------------------------------
__device__ __forceinline__ uint32_t smem_u32(const void* p) {
    uint32_t a;
    asm("{ .reg .u64 t; cvta.to.shared.u64 t, %1; cvt.u32.u64 %0, t; }" : "=r"(a) : "l"(p));
    return a;
}

#define SWZ(x) ((x) ^ (((x) >> 3) & 0x70))

__device__ __forceinline__ void bulk_ld(uint32_t dst, const void* src,
                                        uint32_t bytes, uint32_t mbar) {
    asm volatile(
        "cp.async.bulk.shared::cluster.global.mbarrier::complete_tx::bytes "
        "[%0], [%1], %2, [%3];"
        :: "r"(dst), "l"(src), "r"(bytes), "r"(mbar) : "memory");
}

__device__ __forceinline__ void expect_tx(uint32_t mbar, uint32_t bytes) {
    asm volatile("mbarrier.arrive.expect_tx.shared.b64 _, [%0], %1;"
                 :: "r"(mbar), "r"(bytes) : "memory");
}

__device__ __forceinline__ void mbar_init(uint32_t addr, uint32_t cnt) {
    asm volatile("mbarrier.init.shared.b64 [%0], %1;" :: "r"(addr), "r"(cnt) : "memory");
}

__device__ __forceinline__ void mbar_arrive(uint32_t addr) {
    asm volatile("mbarrier.arrive.shared.b64 _, [%0];" :: "r"(addr) : "memory");
}

__device__ __forceinline__ void mbar_wait(uint32_t addr, uint32_t parity) {
    asm volatile(
        "{\n\t.reg .pred P1;\n\t"
        "WAIT_%=:\n\t"
        "mbarrier.try_wait.parity.acquire.cta.shared::cta.b64 P1, [%0], %1, 0x989680;\n\t"
        "@P1 bra.uni DONE_%=;\n\t"
        "bra.uni WAIT_%=;\n\t"
        "DONE_%=:\n\t}"
        :: "r"(addr), "r"(parity) : "memory");
}

__device__ __forceinline__ void ldsm_x4(uint32_t addr, uint32_t& r0, uint32_t& r1,
                                        uint32_t& r2, uint32_t& r3) {
    asm volatile("ldmatrix.sync.aligned.m8n8.x4.shared.b16 {%0,%1,%2,%3}, [%4];"
                 : "=r"(r0), "=r"(r1), "=r"(r2), "=r"(r3) : "r"(addr));
}

// ---------------------------------------------------------------------------
// Prep 1: fake-quantize x -> int8, tiled+swizzled layout. 16 elems/thread.
// ---------------------------------------------------------------------------
__device__ __forceinline__ uint32_t q4pack(float4 v, float inv) {
    int a = (int)fminf(fmaxf(rintf(v.x * inv), -127.f), 127.f);
    int b = (int)fminf(fmaxf(rintf(v.y * inv), -127.f), 127.f);
    int c = (int)fminf(fmaxf(rintf(v.z * inv), -127.f), 127.f);
    int d = (int)fminf(fmaxf(rintf(v.w * inv), -127.f), 127.f);
    return (a & 255) | ((b & 255) << 8) | ((c & 255) << 16) | ((d & 255) << 24);
}

__global__ void quant_x_kernel(const float* __restrict__ x,
                               const float* __restrict__ act_scale) {
    int idx = blockIdx.x * blockDim.x + threadIdx.x;   // [0, MTOT*IDIM/16)
    int m = idx >> 8;                                  // 256 16B chunks per row
    int c = idx & 255;
    const float4* xp = reinterpret_cast<const float4*>(x + (size_t)m * IDIM + c * 16);
    float s = act_scale[m & (SEQ - 1)];
    float inv = __fdiv_rn(1.0f, s);
    uint4 pk;
    pk.x = q4pack(xp[0], inv);
    pk.y = q4pack(xp[1], inv);
    pk.z = q4pack(xp[2], inv);
    pk.w = q4pack(xp[3], inv);
    int mt = m >> 7, row = m & 127, kc = c >> 3, cc = c & 7;
    *reinterpret_cast<uint4*>(g_Xt8 + (size_t)(mt * 32 + kc) * TILE_BYTES +
                              SWZ((uint32_t)(row * 128 + cc * 16))) = pk;
}

// ---------------------------------------------------------------------------
// Prep 2: 4-bit weights -> int8 (nib - zero), tiled+swizzled. 16 weights/thread.
// ---------------------------------------------------------------------------
__device__ __forceinline__ uint32_t dq4pack(int qa, int qb, int z) {
    int w0 = (qa & 15) - z, w1 = ((qa >> 4) & 15) - z;
    int w2 = (qb & 15) - z, w3 = ((qb >> 4) & 15) - z;
    return (w0 & 255) | ((w1 & 255) << 8) | ((w2 & 255) << 16) | ((w3 & 255) << 24);
}

__global__ void dequant_w_kernel(const int* __restrict__ qw,
                                 const int* __restrict__ wzero) {
    int idx = blockIdx.x * blockDim.x + threadIdx.x;   // [0, ODIM*IDIM/16)
    int o = idx >> 8;
    int c = idx & 255;
    const int4* qp = reinterpret_cast<const int4*>(qw + (size_t)o * 2048 + c * 8);
    int4 qa = qp[0], qb = qp[1];
    int g = c >> 3;                                    // 16 weights stay in one G=128 group
    int z = wzero[o * 32 + g];
    uint4 pk;
    pk.x = dq4pack(qa.x, qa.y, z);
    pk.y = dq4pack(qa.z, qa.w, z);
    pk.z = dq4pack(qb.x, qb.y, z);
    pk.w = dq4pack(qb.z, qb.w, z);
    int nt = o >> 7, row = o & 127, kc = c >> 3, cc = c & 7;
    *reinterpret_cast<uint4*>(g_Wt8 + (size_t)(nt * 32 + kc) * TILE_BYTES +
                              SWZ((uint32_t)(row * 128 + cc * 16))) = pk;
}

// ---------------------------------------------------------------------------
// Prep 3: transpose wscale [O, 32] -> [32, O] for contiguous per-chunk loads.
// ---------------------------------------------------------------------------
__global__ void wst_kernel(const float* __restrict__ wscale) {
    int idx = blockIdx.x * blockDim.x + threadIdx.x;   // 131072
    int g = idx >> 12;
    int n = idx & 4095;
    g_WsT[g * ODIM + n] = wscale[n * 32 + g];
}

// ---------------------------------------------------------------------------
// GEMM: out[m,n] = s[m] * sum_g ws[n,g] * (sum_{k in g} Xint[m,k]*Wint[n,k]) + bias[n]
// int8 mma.sync m16n8k32, CTA 128x256, 8 warps x (64x64), 4-stage bulk pipeline.
// Group fold per chunk (G = KC = 128), exact int32 -> f32 conversion.
// ---------------------------------------------------------------------------
__global__ void __launch_bounds__(256, 1)
gemm_s8_kernel(const float* __restrict__ act_scale,
               const float* __restrict__ bias,
               float* __restrict__ out) {
    extern __shared__ char smem[];
    uint32_t sbase = smem_u32(smem);
    int tid = threadIdx.x;
    int wid = tid >> 5;
    int lid = tid & 31;

    int mt = blockIdx.x >> 4;          // 64 m-tiles (consecutive CTAs share A)
    int nt = blockIdx.x & 15;          // 16 n-tiles of 256
    int m0 = mt * 128;
    int n0 = nt * 256;
    int wm = wid & 1;                  // warp 64-row block
    int wn = wid >> 1;                 // warp 64-col block

    if (tid == 0) {
#pragma unroll
        for (int s = 0; s < F_STAGES; ++s) {
            mbar_init(sbase + SMEM_FULL + 8 * s, 1u);
            mbar_init(sbase + SMEM_EMPTY + 8 * s, 256u);
        }
    }
    __syncthreads();

    const char* Asrc  = reinterpret_cast<const char*>(g_Xt8) + (size_t)mt * 32 * TILE_BYTES;
    const char* B0src = reinterpret_cast<const char*>(g_Wt8) + (size_t)(2 * nt) * 32 * TILE_BYTES;
    const char* B1src = reinterpret_cast<const char*>(g_Wt8) + (size_t)(2 * nt + 1) * 32 * TILE_BYTES;
    const char* Wsrc  = reinterpret_cast<const char*>(g_WsT) + (size_t)n0 * 4;

    if (tid == 0) {
#pragma unroll
        for (int k = 0; k < F_STAGES; ++k) {
            uint32_t fb  = sbase + SMEM_FULL + 8 * k;
            uint32_t stg = sbase + SMEM_DATA + k * STAGE_BYTES;
            expect_tx(fb, 3 * TILE_BYTES + WS_BYTES);
            bulk_ld(stg,                  Asrc  + (size_t)k * TILE_BYTES, TILE_BYTES, fb);
            bulk_ld(stg + TILE_BYTES,     B0src + (size_t)k * TILE_BYTES, TILE_BYTES, fb);
            bulk_ld(stg + 2 * TILE_BYTES, B1src + (size_t)k * TILE_BYTES, TILE_BYTES, fb);
            bulk_ld(stg + 3 * TILE_BYTES, Wsrc  + (size_t)k * (ODIM * 4), WS_BYTES, fb);
        }
    }

    // ldmatrix address components.
    // A frag (m16k32): mat0 rows0-7 kb[0:16), mat1 rows8-15 kb[0:16), mat2/3 kb[16:32).
    int arow_l = ((lid >> 3) & 1) * 8 + (lid & 7);
    uint32_t akb = (uint32_t)((lid >> 4) * 16);
    uint32_t aRow[4], aXor[4];
#pragma unroll
    for (int t = 0; t < 4; ++t) {
        int r = wm * 64 + t * 16 + arow_l;
        aRow[t] = (uint32_t)(r * 128);
        aXor[t] = (uint32_t)((r & 7) << 4);
    }
    // B frag (n8k32 pairs): mat0 n0-7 kb0, mat1 n0-7 kb16, mat2 n8-15 kb0, mat3 n8-15 kb16.
    int bnb = ((lid >> 4) & 1) * 8 + (lid & 7);
    uint32_t bkb = (uint32_t)(((lid >> 3) & 1) * 16);
    uint32_t bOff[4], bXor[4];
#pragma unroll
    for (int hj = 0; hj < 4; ++hj) {
        int nl = wn * 64 + (hj >> 1) * 32 + (hj & 1) * 16 + bnb;   // 0..255
        bOff[hj] = (uint32_t)((nl >> 7) * TILE_BYTES + (nl & 127) * 128);
        bXor[hj] = (uint32_t)((nl & 7) << 4);
    }
    uint32_t wsBase = (uint32_t)((wn * 64 + (lid & 3) * 2) * 4);

    float facc[4][8][4];
#pragma unroll
    for (int t = 0; t < 4; ++t)
#pragma unroll
        for (int u = 0; u < 8; ++u)
#pragma unroll
            for (int e = 0; e < 4; ++e) facc[t][u][e] = 0.0f;

    uint32_t zz = 0;

    for (int k = 0; k < NCHUNK; ++k) {
        int st = k & (F_STAGES - 1);
        uint32_t par = (uint32_t)((k >> 2) & 1);
        mbar_wait(sbase + SMEM_FULL + 8 * st, par);

        uint32_t sA  = sbase + SMEM_DATA + st * STAGE_BYTES;
        uint32_t sB  = sA + TILE_BYTES;
        uint32_t sWs = sA + 3 * TILE_BYTES;

#pragma unroll
        for (int h = 0; h < 2; ++h) {
            int iacc[4][4][4];
#pragma unroll
            for (int ks = 0; ks < 4; ++ks) {
                uint32_t cb = (uint32_t)(ks * 32);
                uint32_t a[4][4];
#pragma unroll
                for (int t = 0; t < 4; ++t)
                    ldsm_x4(sA + aRow[t] + ((cb + akb) ^ aXor[t]),
                            a[t][0], a[t][1], a[t][2], a[t][3]);
                uint32_t b[4][2];
#pragma unroll
                for (int j = 0; j < 2; ++j) {
                    uint32_t r0, r1, r2, r3;
                    int hj = h * 2 + j;
                    ldsm_x4(sB + bOff[hj] + ((cb + bkb) ^ bXor[hj]), r0, r1, r2, r3);
                    b[2 * j][0] = r0;     b[2 * j][1] = r1;
                    b[2 * j + 1][0] = r2; b[2 * j + 1][1] = r3;
                }
#pragma unroll
                for (int t = 0; t < 4; ++t)
#pragma unroll
                    for (int uu = 0; uu < 4; ++uu) {
                        if (ks == 0) {
                            asm volatile(
                                "mma.sync.aligned.m16n8k32.row.col.s32.s8.s8.s32 "
                                "{%0,%1,%2,%3}, {%4,%5,%6,%7}, {%8,%9}, {%10,%10,%10,%10};"
                                : "=r"(iacc[t][uu][0]), "=r"(iacc[t][uu][1]),
                                  "=r"(iacc[t][uu][2]), "=r"(iacc[t][uu][3])
                                : "r"(a[t][0]), "r"(a[t][1]), "r"(a[t][2]), "r"(a[t][3]),
                                  "r"(b[uu][0]), "r"(b[uu][1]), "r"(zz));
                        } else {
                            asm volatile(
                                "mma.sync.aligned.m16n8k32.row.col.s32.s8.s8.s32 "
                                "{%0,%1,%2,%3}, {%4,%5,%6,%7}, {%8,%9}, {%0,%1,%2,%3};"
                                : "+r"(iacc[t][uu][0]), "+r"(iacc[t][uu][1]),
                                  "+r"(iacc[t][uu][2]), "+r"(iacc[t][uu][3])
                                : "r"(a[t][0]), "r"(a[t][1]), "r"(a[t][2]), "r"(a[t][3]),
                                  "r"(b[uu][0]), "r"(b[uu][1]));
                        }
                    }
            }
            // Group fold: exact (|iacc| <= 127*15*128 < 2^23).
#pragma unroll
            for (int uu = 0; uu < 4; ++uu) {
                float2 ws;
                asm volatile("ld.shared.v2.f32 {%0,%1}, [%2];"
                             : "=f"(ws.x), "=f"(ws.y)
                             : "r"(sWs + wsBase + (uint32_t)((h * 32 + uu * 8) * 4)));
                int u = h * 4 + uu;
#pragma unroll
                for (int t = 0; t < 4; ++t) {
                    facc[t][u][0] += __int2float_rn(iacc[t][uu][0]) * ws.x;
                    facc[t][u][1] += __int2float_rn(iacc[t][uu][1]) * ws.y;
                    facc[t][u][2] += __int2float_rn(iacc[t][uu][2]) * ws.x;
                    facc[t][u][3] += __int2float_rn(iacc[t][uu][3]) * ws.y;
                }
            }
        }

        mbar_arrive(sbase + SMEM_EMPTY + 8 * st);
        if (tid == 0 && k + F_STAGES < NCHUNK) {
            mbar_wait(sbase + SMEM_EMPTY + 8 * st, par);
            uint32_t fb  = sbase + SMEM_FULL + 8 * st;
            uint32_t stg = sbase + SMEM_DATA + st * STAGE_BYTES;
            int kn = k + F_STAGES;
            expect_tx(fb, 3 * TILE_BYTES + WS_BYTES);
            bulk_ld(stg,                  Asrc  + (size_t)kn * TILE_BYTES, TILE_BYTES, fb);
            bulk_ld(stg + TILE_BYTES,     B0src + (size_t)kn * TILE_BYTES, TILE_BYTES, fb);
            bulk_ld(stg + 2 * TILE_BYTES, B1src + (size_t)kn * TILE_BYTES, TILE_BYTES, fb);
            bulk_ld(stg + 3 * TILE_BYTES, Wsrc  + (size_t)kn * (ODIM * 4), WS_BYTES, fb);
        }
    }

    // Epilogue: d-frag (t,u): rows m0+wm*64+16t+qr (+8), cols n0+wn*64+8u+qc (+1).
    int qr = lid >> 2;
    int qc = (lid & 3) * 2;
#pragma unroll
    for (int t = 0; t < 4; ++t) {
        int mA = m0 + wm * 64 + t * 16 + qr;
        int mB = mA + 8;
        float sA_ = act_scale[mA & (SEQ - 1)];
        float sB_ = act_scale[mB & (SEQ - 1)];
#pragma unroll
        for (int u = 0; u < 8; ++u) {
            int n = n0 + wn * 64 + u * 8 + qc;
            float b0 = bias[n], b1 = bias[n + 1];
            float2 v0, v1;
            v0.x = facc[t][u][0] * sA_ + b0;
            v0.y = facc[t][u][1] * sA_ + b1;
            v1.x = facc[t][u][2] * sB_ + b0;
            v1.y = facc[t][u][3] * sB_ + b1;
            *reinterpret_cast<float2*>(out + (size_t)mA * ODIM + n) = v0;
            *reinterpret_cast<float2*>(out + (size_t)mB * ODIM + n) = v1;
        }
    }
}

// ---------------------------------------------------------------------------
extern "C" void kernel_launch(void* const* d_in, const int* in_sizes, int n_in,
                              void* d_out, int out_size) {
    const float* x            = (const float*)d_in[0];
    const int*   qweight      = (const int*)d_in[1];
    const float* act_scale    = (const float*)d_in[2];
    const float* weight_scale = (const float*)d_in[3];
    const int*   weight_zero  = (const int*)d_in[4];
    const float* bias         = (const float*)d_in[5];
    float* out = (float*)d_out;

    cudaFuncSetAttribute(gemm_s8_kernel,
                         cudaFuncAttributeMaxDynamicSharedMemorySize, SMEM_TOTAL);

    quant_x_kernel<<<(MTOT * IDIM / 16) / 256, 256>>>(x, act_scale);
    dequant_w_kernel<<<(ODIM * IDIM / 16) / 256, 256>>>(qweight, weight_zero);
    wst_kernel<<<(32 * ODIM) / 256, 256>>>(weight_scale);
    gemm_s8_kernel<<<(MTOT / 128) * (ODIM / 256), 256, SMEM_TOTAL>>>(act_scale, bias, out);
}

// round 7
// speedup vs baseline: 3.1694x; 3.1694x over previous
#include <cuda_runtime.h>
#include <cuda_fp16.h>
#include <cstdint>

// Problem constants
#define ODIM 4096
#define IDIM 4096
#define MTOT 8192   // B*S = 4*2048
#define SEQ  2048

#define KC 64                  // K elems per chunk (64 fp16 = 128B row = SW128 atom)
#define NCHUNK (IDIM / KC)     // 64
#define NSTEP  (NCHUNK * 4)    // 256 k16-steps
#define F_STAGES 4

// Shared memory layout
#define SMEM_FULL  8           // 4 x 8B full barriers (complete_tx)
#define SMEM_EMPTY 64          // 4 x 8B empty barriers (count=8)
#define SMEM_DATA  1024
#define OP_BYTES   16384       // 128 rows x 128B
#define STAGE_BYTES 49152      // A + B0 + B1
#define SMEM_TOTAL  (1024 + F_STAGES * STAGE_BYTES)   // 197632

// Tiled, pre-swizzled fp16 operands: (row128-tile, kchunk64) = 16KB contiguous.
__device__ uint4 g_Xt[(size_t)MTOT * IDIM / 8];   // 64 MB
__device__ uint4 g_Wt[(size_t)ODIM * IDIM / 8];   // 32 MB

// ---------------------------------------------------------------------------
// helpers
// ---------------------------------------------------------------------------
__device__ __forceinline__ uint32_t smem_u32(const void* p) {
    uint32_t a;
    asm("{ .reg .u64 t; cvta.to.shared.u64 t, %1; cvt.u32.u64 %0, t; }" : "=r"(a) : "l"(p));
    return a;
}

#define SWZ(x) ((x) ^ (((x) >> 3) & 0x70))

__device__ __forceinline__ void bulk_ld(uint32_t dst, const void* src,
                                        uint32_t bytes, uint32_t mbar) {
    asm volatile(
        "cp.async.bulk.shared::cluster.global.mbarrier::complete_tx::bytes "
        "[%0], [%1], %2, [%3];"
        :: "r"(dst), "l"(src), "r"(bytes), "r"(mbar) : "memory");
}

__device__ __forceinline__ void expect_tx(uint32_t mbar, uint32_t bytes) {
    asm volatile("mbarrier.arrive.expect_tx.shared.b64 _, [%0], %1;"
                 :: "r"(mbar), "r"(bytes) : "memory");
}

__device__ __forceinline__ void mbar_init(uint32_t addr, uint32_t cnt) {
    asm volatile("mbarrier.init.shared.b64 [%0], %1;" :: "r"(addr), "r"(cnt) : "memory");
}

__device__ __forceinline__ void mbar_arrive(uint32_t addr) {
    asm volatile("mbarrier.arrive.shared.b64 _, [%0];" :: "r"(addr) : "memory");
}

__device__ __forceinline__ void mbar_wait(uint32_t addr, uint32_t parity) {
    asm volatile(
        "{\n\t.reg .pred P1;\n\t"
        "WAIT_%=:\n\t"
        "mbarrier.try_wait.parity.acquire.cta.shared::cta.b64 P1, [%0], %1, 0x989680;\n\t"
        "@P1 bra.uni DONE_%=;\n\t"
        "bra.uni WAIT_%=;\n\t"
        "DONE_%=:\n\t}"
        :: "r"(addr), "r"(parity) : "memory");
}

__device__ __forceinline__ void ldsm_x4(uint32_t addr, uint32_t& r0, uint32_t& r1,
                                        uint32_t& r2, uint32_t& r3) {
    asm volatile("ldmatrix.sync.aligned.m8n8.x4.shared.b16 {%0,%1,%2,%3}, [%4];"
                 : "=r"(r0), "=r"(r1), "=r"(r2), "=r"(r3) : "r"(addr));
}

// ---------------------------------------------------------------------------
// Prep 1: fake-quantize x -> integer-valued fp16, tiled+swizzled layout.
// ---------------------------------------------------------------------------
__global__ void quant_x_kernel(const float* __restrict__ x,
                               const float* __restrict__ act_scale) {
    int idx = blockIdx.x * blockDim.x + threadIdx.x;
    int m = idx >> 9;            // 512 chunks of 8 elems per row
    int c = idx & 511;
    const float4* xp = reinterpret_cast<const float4*>(x + (size_t)m * IDIM + c * 8);
    float4 v0 = xp[0];
    float4 v1 = xp[1];
    float s = act_scale[m & (SEQ - 1)];
    float inv = __fdiv_rn(1.0f, s);
    float q0 = fminf(fmaxf(rintf(v0.x * inv), -127.f), 127.f);
    float q1 = fminf(fmaxf(rintf(v0.y * inv), -127.f), 127.f);
    float q2 = fminf(fmaxf(rintf(v0.z * inv), -127.f), 127.f);
    float q3 = fminf(fmaxf(rintf(v0.w * inv), -127.f), 127.f);
    float q4 = fminf(fmaxf(rintf(v1.x * inv), -127.f), 127.f);
    float q5 = fminf(fmaxf(rintf(v1.y * inv), -127.f), 127.f);
    float q6 = fminf(fmaxf(rintf(v1.z * inv), -127.f), 127.f);
    float q7 = fminf(fmaxf(rintf(v1.w * inv), -127.f), 127.f);
    __half2 h0 = __floats2half2_rn(q0, q1);
    __half2 h1 = __floats2half2_rn(q2, q3);
    __half2 h2 = __floats2half2_rn(q4, q5);
    __half2 h3 = __floats2half2_rn(q6, q7);
    uint4 pk;
    pk.x = *reinterpret_cast<uint32_t*>(&h0);
    pk.y = *reinterpret_cast<uint32_t*>(&h1);
    pk.z = *reinterpret_cast<uint32_t*>(&h2);
    pk.w = *reinterpret_cast<uint32_t*>(&h3);
    int mt = m >> 7, row = m & 127, kc = c >> 3, cc = c & 7;
    g_Xt[(size_t)(mt * 64 + kc) * 1024 + (SWZ((uint32_t)(row * 128 + cc * 16)) >> 4)] = pk;
}

// ---------------------------------------------------------------------------
// Prep 2: dequantize 4-bit weights -> fp16, tiled+swizzled layout.
// ---------------------------------------------------------------------------
__global__ void dequant_w_kernel(const int* __restrict__ qw,
                                 const float* __restrict__ wscale,
                                 const int* __restrict__ wzero) {
    int idx = blockIdx.x * blockDim.x + threadIdx.x;
    int o = idx >> 9;
    int c = idx & 511;
    int4 q = reinterpret_cast<const int4*>(qw + (size_t)o * (IDIM / 2) + c * 4)[0];
    int g = c >> 4;
    float z  = (float)wzero[o * 32 + g];
    float ws = wscale[o * 32 + g];
    __half2 h0 = __floats2half2_rn(((float)(q.x & 15) - z) * ws,
                                   ((float)((q.x >> 4) & 15) - z) * ws);
    __half2 h1 = __floats2half2_rn(((float)(q.y & 15) - z) * ws,
                                   ((float)((q.y >> 4) & 15) - z) * ws);
    __half2 h2 = __floats2half2_rn(((float)(q.z & 15) - z) * ws,
                                   ((float)((q.z >> 4) & 15) - z) * ws);
    __half2 h3 = __floats2half2_rn(((float)(q.w & 15) - z) * ws,
                                   ((float)((q.w >> 4) & 15) - z) * ws);
    uint4 pk;
    pk.x = *reinterpret_cast<uint32_t*>(&h0);
    pk.y = *reinterpret_cast<uint32_t*>(&h1);
    pk.z = *reinterpret_cast<uint32_t*>(&h2);
    pk.w = *reinterpret_cast<uint32_t*>(&h3);
    int nt = o >> 7, row = o & 127, kc = c >> 3, cc = c & 7;
    g_Wt[(size_t)(nt * 64 + kc) * 1024 + (SWZ((uint32_t)(row * 128 + cc * 16)) >> 4)] = pk;
}

// ---------------------------------------------------------------------------
// GEMM: out[m,n] = s[m] * sum_k X[m,k]*W[n,k] + bias[n]
// fp16 mma.sync m16n8k16, CTA 128x256, 8 warps x (64x64), 4-stage bulk pipeline.
// Double-buffered register fragments pipelined across all 256 k16-steps.
// ---------------------------------------------------------------------------
__global__ void __launch_bounds__(256, 1)
gemm_f16_kernel(const float* __restrict__ act_scale,
                const float* __restrict__ bias,
                float* __restrict__ out) {
    extern __shared__ char smem[];
    uint32_t sbase = smem_u32(smem);
    int tid = threadIdx.x;
    int wid = tid >> 5;
    int lid = tid & 31;

    int mt = blockIdx.x >> 4;          // 64 m-tiles (consecutive CTAs share A tile)
    int nt = blockIdx.x & 15;          // 16 n-tiles of 256
    int m0 = mt * 128;
    int n0 = nt * 256;
    int wm = wid & 1;
    int wn = wid >> 1;

    if (tid == 0) {
#pragma unroll
        for (int s = 0; s < F_STAGES; ++s) {
            mbar_init(sbase + SMEM_FULL + 8 * s, 1u);
            mbar_init(sbase + SMEM_EMPTY + 8 * s, 8u);   // one arrive per warp
        }
    }
    __syncthreads();

    const char* Asrc  = reinterpret_cast<const char*>(g_Xt) + (size_t)mt * 64 * OP_BYTES;
    const char* B0src = reinterpret_cast<const char*>(g_Wt) + (size_t)(2 * nt) * 64 * OP_BYTES;
    const char* B1src = reinterpret_cast<const char*>(g_Wt) + (size_t)(2 * nt + 1) * 64 * OP_BYTES;

    if (tid == 0) {
#pragma unroll
        for (int k = 0; k < F_STAGES; ++k) {
            uint32_t fb  = sbase + SMEM_FULL + 8 * k;
            uint32_t stg = sbase + SMEM_DATA + k * STAGE_BYTES;
            expect_tx(fb, 3 * OP_BYTES);
            bulk_ld(stg,                Asrc  + (size_t)k * OP_BYTES, OP_BYTES, fb);
            bulk_ld(stg + OP_BYTES,     B0src + (size_t)k * OP_BYTES, OP_BYTES, fb);
            bulk_ld(stg + 2 * OP_BYTES, B1src + (size_t)k * OP_BYTES, OP_BYTES, fb);
        }
    }

    // Lane-constant ldmatrix address components.
    int lrow = lid & 15;
    uint32_t lcol16 = (uint32_t)((lid >> 4) * 16);
    // A: rows wm*64 + t*16 + lrow ; aRow0 + t*2048 ; xor nibble constant.
    uint32_t aRow0 = (uint32_t)((wm * 64 + lrow) * 128);
    uint32_t aXor  = (uint32_t)((lrow & 7) << 4);
    // B: n = wn*64 + p*16 + lrow ; within one 16KB half per warp (wn>>1).
    uint32_t bOff0 = (uint32_t)((wn >> 1) * OP_BYTES +
                                (((wn & 1) * 64 + lrow) * 128));
    uint32_t bXor  = aXor;

    float acc[4][8][4];
#pragma unroll
    for (int t = 0; t < 4; ++t)
#pragma unroll
        for (int u = 0; u < 8; ++u)
#pragma unroll
            for (int e = 0; e < 4; ++e) acc[t][u][e] = 0.0f;

    uint32_t afr[2][4][4];
    uint32_t bfr[2][8][2];

    // load fragments for k16-step i into buffer bi
#define LOAD_STEP(i_, bi_)                                                        \
    do {                                                                          \
        uint32_t stg_ = sbase + SMEM_DATA + (uint32_t)((((i_) >> 2) & 3) * STAGE_BYTES); \
        uint32_t cb_  = (uint32_t)(((i_) & 3) * 32) + lcol16;                     \
        uint32_t sB_  = stg_ + OP_BYTES;                                          \
        _Pragma("unroll")                                                         \
        for (int t_ = 0; t_ < 4; ++t_)                                            \
            ldsm_x4(stg_ + aRow0 + (uint32_t)(t_ * 2048) + (cb_ ^ aXor),          \
                    afr[bi_][t_][0], afr[bi_][t_][1],                             \
                    afr[bi_][t_][2], afr[bi_][t_][3]);                            \
        _Pragma("unroll")                                                         \
        for (int p_ = 0; p_ < 4; ++p_) {                                          \
            uint32_t r0_, r1_, r2_, r3_;                                          \
            ldsm_x4(sB_ + bOff0 + (uint32_t)(p_ * 2048) + (cb_ ^ bXor),           \
                    r0_, r1_, r2_, r3_);                                          \
            bfr[bi_][2 * p_][0] = r0_;     bfr[bi_][2 * p_][1] = r2_;             \
            bfr[bi_][2 * p_ + 1][0] = r1_; bfr[bi_][2 * p_ + 1][1] = r3_;         \
        }                                                                         \
    } while (0)

    // Prologue: wait chunk 0, load step 0.
    mbar_wait(sbase + SMEM_FULL, 0u);
    LOAD_STEP(0, 0);

#pragma unroll 4
    for (int i = 0; i < NSTEP; ++i) {
        int cur = i & 1;
        int inx = i + 1;
        if (inx < NSTEP) {
            if ((inx & 3) == 0) {
                int nc = inx >> 2;
                mbar_wait(sbase + SMEM_FULL + 8 * (nc & 3), (uint32_t)((nc >> 2) & 1));
            }
            LOAD_STEP(inx, cur ^ 1);
        }
#pragma unroll
        for (int t = 0; t < 4; ++t)
#pragma unroll
            for (int u = 0; u < 8; ++u) {
                asm volatile(
                    "mma.sync.aligned.m16n8k16.row.col.f32.f16.f16.f32 "
                    "{%0,%1,%2,%3}, {%4,%5,%6,%7}, {%8,%9}, {%0,%1,%2,%3};"
                    : "+f"(acc[t][u][0]), "+f"(acc[t][u][1]),
                      "+f"(acc[t][u][2]), "+f"(acc[t][u][3])
                    : "r"(afr[cur][t][0]), "r"(afr[cur][t][1]),
                      "r"(afr[cur][t][2]), "r"(afr[cur][t][3]),
                      "r"(bfr[cur][u][0]), "r"(bfr[cur][u][1]));
            }
        if ((i & 3) == 3) {
            int c = i >> 2;
            int st = c & 3;
            if (lid == 0) mbar_arrive(sbase + SMEM_EMPTY + 8 * st);
            if (tid == 0 && c + F_STAGES < NCHUNK) {
                mbar_wait(sbase + SMEM_EMPTY + 8 * st, (uint32_t)((c >> 2) & 1));
                uint32_t fb  = sbase + SMEM_FULL + 8 * st;
                uint32_t stg = sbase + SMEM_DATA + st * STAGE_BYTES;
                int kn = c + F_STAGES;
                expect_tx(fb, 3 * OP_BYTES);
                bulk_ld(stg,                Asrc  + (size_t)kn * OP_BYTES, OP_BYTES, fb);
                bulk_ld(stg + OP_BYTES,     B0src + (size_t)kn * OP_BYTES, OP_BYTES, fb);
                bulk_ld(stg + 2 * OP_BYTES, B1src + (size_t)kn * OP_BYTES, OP_BYTES, fb);
            }
        }
    }
#undef LOAD_STEP

    // Epilogue: d-frag (t,u): rows m0+wm*64+16t+qr (+8), cols n0+wn*64+8u+qc (+1).
    int qr = lid >> 2;
    int qc = (lid & 3) * 2;
#pragma unroll
    for (int t = 0; t < 4; ++t) {
        int mA = m0 + wm * 64 + t * 16 + qr;
        int mB = mA + 8;
        float sA_ = act_scale[mA & (SEQ - 1)];
        float sB_ = act_scale[mB & (SEQ - 1)];
#pragma unroll
        for (int u = 0; u < 8; ++u) {
            int n = n0 + wn * 64 + u * 8 + qc;
            float b0 = bias[n], b1 = bias[n + 1];
            float2 v0, v1;
            v0.x = acc[t][u][0] * sA_ + b0;
            v0.y = acc[t][u][1] * sA_ + b1;
            v1.x = acc[t][u][2] * sB_ + b0;
            v1.y = acc[t][u][3] * sB_ + b1;
            *reinterpret_cast<float2*>(out + (size_t)mA * ODIM + n) = v0;
            *reinterpret_cast<float2*>(out + (size_t)mB * ODIM + n) = v1;
        }
    }
}

// ---------------------------------------------------------------------------
extern "C" void kernel_launch(void* const* d_in, const int* in_sizes, int n_in,
                              void* d_out, int out_size) {
    const float* x            = (const float*)d_in[0];
    const int*   qweight      = (const int*)d_in[1];
    const float* act_scale    = (const float*)d_in[2];
    const float* weight_scale = (const float*)d_in[3];
    const int*   weight_zero  = (const int*)d_in[4];
    const float* bias         = (const float*)d_in[5];
    float* out = (float*)d_out;

    cudaFuncSetAttribute(gemm_f16_kernel,
                         cudaFuncAttributeMaxDynamicSharedMemorySize, SMEM_TOTAL);

    quant_x_kernel<<<(MTOT * IDIM / 8) / 256, 256>>>(x, act_scale);
    dequant_w_kernel<<<(ODIM * IDIM / 8) / 256, 256>>>(qweight, weight_scale, weight_zero);
    gemm_f16_kernel<<<(MTOT / 128) * (ODIM / 256), 256, SMEM_TOTAL>>>(act_scale, bias, out);
}